// round 5
// baseline (speedup 1.0000x reference)
#include <cuda_runtime.h>
#include <cstdint>

// ---------------- problem constants ----------------
#define B_   32
#define H_   168
#define N_   512
#define F_   8
#define P_   24
#define KIN_ (N_ * F_)   // 4096
#define G4N_ (4 * N_)    // 2048
#define MR_  (B_ * H_)   // 5376
#define RGRID 128        // recurrence grid (must all be co-resident; 128 <= 148 SMs)

// ---------------- device scratch (no runtime allocation allowed) ----------------
__device__ float d_xr[(size_t)MR_ * N_];        // 11 MB
__device__ float d_xk[(size_t)MR_ * G4N_];      // 44 MB (includes lstm_b)
__device__ float d_wdec[(size_t)N_ * G4N_];     // 4 MB  (lstm_k + lstm_rk)
__device__ float d_h[2][N_ * B_];               // h transposed: [n][b], double buffered
__device__ float d_preds[(size_t)B_ * P_ * N_]; // 1.5 MB
__device__ unsigned int g_arrive;               // monotonic barrier counters (never reset)
__device__ unsigned int g_release;

// ---------------- tf32 helpers ----------------
__device__ __forceinline__ unsigned f2tf(float x) {
    unsigned r;
    asm("cvt.rna.tf32.f32 %0, %1;" : "=r"(r) : "f"(x));
    return r;
}

// ======================================================================
// Generic C[M,N] = A[M,K] @ B[K,N] + bias[N], tf32 tensor cores.
// Requires M%128==0, N%64==0, K%32==0 (true for all 3 call sites).
// Block tile 128x64, 8 warps (4x2), warp tile 32x32, K-tile 32.
// ======================================================================
#define BM 128
#define BN 64
#define BKt 32

__global__ __launch_bounds__(256) void gemm_tf32(
    const float* __restrict__ A, const float* __restrict__ Bw,
    const float* __restrict__ bias, float* __restrict__ C,
    int M, int N, int K)
{
    __shared__ float As[BM][BKt + 4];  // pad 4 -> conflict-free frag loads
    __shared__ float Bs[BKt][BN + 4];

    const int tid  = threadIdx.x;
    const int lane = tid & 31;
    const int warp = tid >> 5;
    const int wm = warp & 3;   // 0..3  (M direction)
    const int wn = warp >> 2;  // 0..1  (N direction)
    const int bm = blockIdx.y, bn = blockIdx.x;
    const int g  = lane >> 2;  // groupID        (0..7)
    const int tg = lane & 3;   // thread-in-group (0..3)

    const float* Ag = A + (size_t)bm * BM * K;
    const float* Bg = Bw + (size_t)bn * BN;

    float acc[2][4][4];
#pragma unroll
    for (int i = 0; i < 2; i++)
#pragma unroll
        for (int j = 0; j < 4; j++)
#pragma unroll
            for (int r = 0; r < 4; r++) acc[i][j][r] = 0.f;

    for (int kt = 0; kt < K; kt += BKt) {
        // ---- stage A tile (128x32): 4 float4 per thread ----
#pragma unroll
        for (int i = 0; i < 4; i++) {
            int f4  = tid + i * 256;
            int row = f4 >> 3;            // 8 float4 per row
            int kc  = (f4 & 7) << 2;
            float4 v = *(const float4*)(Ag + (size_t)row * K + kt + kc);
            As[row][kc + 0] = __uint_as_float(f2tf(v.x));
            As[row][kc + 1] = __uint_as_float(f2tf(v.y));
            As[row][kc + 2] = __uint_as_float(f2tf(v.z));
            As[row][kc + 3] = __uint_as_float(f2tf(v.w));
        }
        // ---- stage B tile (32x64): 2 float4 per thread ----
#pragma unroll
        for (int i = 0; i < 2; i++) {
            int f4  = tid + i * 256;
            int row = f4 >> 4;            // 16 float4 per row
            int nc  = (f4 & 15) << 2;
            float4 v = *(const float4*)(Bg + (size_t)(kt + row) * N + nc);
            Bs[row][nc + 0] = __uint_as_float(f2tf(v.x));
            Bs[row][nc + 1] = __uint_as_float(f2tf(v.y));
            Bs[row][nc + 2] = __uint_as_float(f2tf(v.z));
            Bs[row][nc + 3] = __uint_as_float(f2tf(v.w));
        }
        __syncthreads();

#pragma unroll
        for (int ks = 0; ks < 4; ks++) {
            const int k0 = ks * 8;
            unsigned a[2][4], b[4][2];
#pragma unroll
            for (int mi = 0; mi < 2; mi++) {
                int m0 = wm * 32 + mi * 16;
                a[mi][0] = __float_as_uint(As[m0 + g    ][k0 + tg    ]);
                a[mi][1] = __float_as_uint(As[m0 + g + 8][k0 + tg    ]);
                a[mi][2] = __float_as_uint(As[m0 + g    ][k0 + tg + 4]);
                a[mi][3] = __float_as_uint(As[m0 + g + 8][k0 + tg + 4]);
            }
#pragma unroll
            for (int ni = 0; ni < 4; ni++) {
                int n0 = wn * 32 + ni * 8;
                b[ni][0] = __float_as_uint(Bs[k0 + tg    ][n0 + g]);
                b[ni][1] = __float_as_uint(Bs[k0 + tg + 4][n0 + g]);
            }
#pragma unroll
            for (int mi = 0; mi < 2; mi++)
#pragma unroll
                for (int ni = 0; ni < 4; ni++)
                    asm volatile(
                        "mma.sync.aligned.m16n8k8.row.col.f32.tf32.tf32.f32 "
                        "{%0,%1,%2,%3},{%4,%5,%6,%7},{%8,%9},{%0,%1,%2,%3};"
                        : "+f"(acc[mi][ni][0]), "+f"(acc[mi][ni][1]),
                          "+f"(acc[mi][ni][2]), "+f"(acc[mi][ni][3])
                        : "r"(a[mi][0]), "r"(a[mi][1]), "r"(a[mi][2]), "r"(a[mi][3]),
                          "r"(b[ni][0]), "r"(b[ni][1]));
        }
        __syncthreads();
    }

    // ---- epilogue: add bias, write float2 pairs ----
#pragma unroll
    for (int mi = 0; mi < 2; mi++) {
        int r0 = bm * BM + wm * 32 + mi * 16 + g;
#pragma unroll
        for (int ni = 0; ni < 4; ni++) {
            int c0 = bn * BN + wn * 32 + ni * 8 + tg * 2;
            float b0 = bias[c0], b1 = bias[c0 + 1];
            *(float2*)(C + (size_t)r0 * N + c0) =
                make_float2(acc[mi][ni][0] + b0, acc[mi][ni][1] + b1);
            *(float2*)(C + (size_t)(r0 + 8) * N + c0) =
                make_float2(acc[mi][ni][2] + b0, acc[mi][ni][3] + b1);
        }
    }
}

// ======================================================================
// Wdec = lstm_k + lstm_rk (elementwise, float4)
// ======================================================================
__global__ void add_w(const float* __restrict__ a, const float* __restrict__ b,
                      float* __restrict__ o, int n4)
{
    int i = blockIdx.x * blockDim.x + threadIdx.x;
    if (i < n4) {
        float4 x = ((const float4*)a)[i];
        float4 y = ((const float4*)b)[i];
        ((float4*)o)[i] = make_float4(x.x + y.x, x.y + y.y, x.z + y.z, x.w + y.w);
    }
}

// ======================================================================
// Persistent recurrence kernel.
// 128 blocks x 128 threads. Block j owns hidden columns [4j, 4j+4).
// Thread (b = tid&31, g = tid>>5) computes z[b][g*512 + 4j + 0..3] (float4 acc).
// c-state lives in a register (cell (b, 4j+g) fixed per thread for all 192 steps).
// h is kept transposed h^T[n][b] in global, double-buffered; one grid barrier/step.
// ======================================================================
__device__ __forceinline__ void grid_barrier()
{
    __syncthreads();
    if (threadIdx.x == 0) {
        __threadfence();  // publish h writes; gpu-scope fence also invalidates L1D
        unsigned my = atomicAdd(&g_arrive, 1u) + 1u;
        unsigned need = (my + RGRID - 1u) / RGRID;
        if ((my % RGRID) == 0u) {
            atomicAdd(&g_release, 1u);
        } else {
            while (((volatile unsigned*)&g_release)[0] < need) { __nanosleep(40); }
        }
        __threadfence();
    }
    __syncthreads();
}

__device__ __forceinline__ float sigf(float x) { return 1.f / (1.f + expf(-x)); }

__global__ __launch_bounds__(128) void recurrence(
    const float* __restrict__ Wenc,   // lstm_rk [512][2048]
    const float* __restrict__ Wdec,   // [512][2048]
    const float* __restrict__ xk,     // [B*H][2048] (bias folded in)
    const float* __restrict__ lb,     // lstm_b [2048]
    float* __restrict__ preds)        // [B][P][N]
{
    extern __shared__ float hsh[];    // 512*32 floats = 64 KB (h^T staged per step)
    __shared__ float zs[4][4][32];    // [gate][q][b]

    const int tid = threadIdx.x;
    const int b = tid & 31;
    const int g = tid >> 5;           // gate in compute phase, q in update phase
    const int nc0 = blockIdx.x * 4;

    // zero own cells of h buffer 0; c state starts at 0
    d_h[0][(nc0 + g) * 32 + b] = 0.f;
    float c = 0.f;
    grid_barrier();

    for (int s = 0; s < H_ + P_; s++) {
        // stage h^T into shared with .cg (bypass possibly-stale L1)
        const float4* hg = (const float4*)d_h[s & 1];
        float4* hs4 = (float4*)hsh;
#pragma unroll
        for (int i = 0; i < (N_ * B_ / 4) / 128; i++)
            hs4[tid + i * 128] = __ldcg(hg + tid + i * 128);
        __syncthreads();

        // init accumulator: encoder -> xk[t] (bias included), decoder -> lstm_b
        float4 acc;
        if (s < H_)
            acc = *(const float4*)(xk + ((size_t)b * H_ + s) * G4N_ + g * N_ + nc0);
        else
            acc = *(const float4*)(lb + g * N_ + nc0);

        const float* W = (s < H_) ? Wenc : Wdec;
        const float* wp = W + g * N_ + nc0;
#pragma unroll 8
        for (int k = 0; k < N_; k++) {
            float hv = hsh[k * 32 + b];
            float4 w = *(const float4*)(wp + (size_t)k * G4N_);
            acc.x = fmaf(hv, w.x, acc.x);
            acc.y = fmaf(hv, w.y, acc.y);
            acc.z = fmaf(hv, w.z, acc.z);
            acc.w = fmaf(hv, w.w, acc.w);
        }

        // exchange gates within block
        zs[g][0][b] = acc.x; zs[g][1][b] = acc.y;
        zs[g][2][b] = acc.z; zs[g][3][b] = acc.w;
        __syncthreads();

        // update cell (b, nc0+q), q == g  (gate order: i, f, g, o)
        const int q = g;
        float iz = zs[0][q][b], fz = zs[1][q][b], gz = zs[2][q][b], oz = zs[3][q][b];
        float ii = sigf(iz), ff = sigf(fz), gg = tanhf(gz), oo = sigf(oz);
        c = ff * c + ii * gg;
        float hn = oo * tanhf(c);
        d_h[(s + 1) & 1][(nc0 + q) * 32 + b] = hn;
        if (s >= H_)
            preds[((size_t)b * P_ + (s - H_)) * N_ + nc0 + q] = hn;

        grid_barrier();
    }
}

// ======================================================================
// launch
// ======================================================================
extern "C" void kernel_launch(void* const* d_in, const int* in_sizes, int n_in,
                              void* d_out, int out_size)
{
    const float* x       = (const float*)d_in[0];
    const float* conv_w  = (const float*)d_in[1];
    const float* conv_b  = (const float*)d_in[2];
    const float* lstm_k  = (const float*)d_in[3];
    const float* lstm_rk = (const float*)d_in[4];
    const float* lstm_b  = (const float*)d_in[5];
    const float* dense_w = (const float*)d_in[6];
    const float* dense_b = (const float*)d_in[7];
    float* out = (float*)d_out;

    float *xr, *xk, *wdec, *preds;
    cudaGetSymbolAddress((void**)&xr,    d_xr);
    cudaGetSymbolAddress((void**)&xk,    d_xk);
    cudaGetSymbolAddress((void**)&wdec,  d_wdec);
    cudaGetSymbolAddress((void**)&preds, d_preds);

    static_assert(N_ * B_ * 4 == 65536, "hsh size");
    cudaFuncSetAttribute(recurrence, cudaFuncAttributeMaxDynamicSharedMemorySize, 65536);

    // 1) xr = reshape(x) @ conv_w + conv_b     [5376,4096]x[4096,512]
    {
        dim3 grid(N_ / BN, MR_ / BM);
        gemm_tf32<<<grid, 256>>>(x, conv_w, conv_b, xr, MR_, N_, KIN_);
    }
    // 2) xk = xr @ lstm_k + lstm_b             [5376,512]x[512,2048]
    {
        dim3 grid(G4N_ / BN, MR_ / BM);
        gemm_tf32<<<grid, 256>>>(xr, lstm_k, lstm_b, xk, MR_, G4N_, N_);
    }
    // 3) Wdec = lstm_k + lstm_rk
    {
        int n4 = (N_ * G4N_) / 4;
        add_w<<<(n4 + 255) / 256, 256>>>(lstm_k, lstm_rk, wdec, n4);
    }
    // 4) encoder (168 steps) + decoder (24 steps), persistent
    recurrence<<<RGRID, 128, 65536>>>(lstm_rk, wdec, xk, lstm_b, preds);
    // 5) out = preds @ dense_w + dense_b       [768,512]x[512,512]
    {
        dim3 grid(N_ / BN, (B_ * P_) / BM);
        gemm_tf32<<<grid, 256>>>(preds, dense_w, dense_b, out, B_ * P_, N_, N_);
    }
}

// round 6
// speedup vs baseline: 5.5870x; 5.5870x over previous
#include <cuda_runtime.h>
#include <cstdint>

// ---------------- problem constants ----------------
#define B_   32
#define H_   168
#define N_   512
#define F_   8
#define P_   24
#define KIN_ (N_ * F_)   // 4096
#define G4N_ (4 * N_)    // 2048
#define MR_  (B_ * H_)   // 5376
#define RGRID 128        // recurrence grid (all co-resident; 128 <= 148 SMs)
#define HS_  516         // hsh row stride (pad: conflict-free, 16B aligned)

typedef unsigned long long ull;

// ---------------- device scratch (no runtime allocation allowed) ----------------
__device__ float d_xr[(size_t)MR_ * N_];        // 11 MB
__device__ float d_xk[(size_t)MR_ * G4N_];      // 44 MB (includes lstm_b)
__device__ float d_wdec[(size_t)N_ * G4N_];     // 4 MB  (lstm_k + lstm_rk)
__device__ float d_h[2][B_ * N_];               // h[b][n], double buffered
__device__ float d_preds[(size_t)B_ * P_ * N_]; // 1.5 MB
__device__ unsigned int g_arrive;               // monotonic barrier counters
__device__ unsigned int g_release;

// ---------------- tf32 helpers ----------------
__device__ __forceinline__ unsigned f2tf(float x) {
    unsigned r;
    asm("cvt.rna.tf32.f32 %0, %1;" : "=r"(r) : "f"(x));
    return r;
}

// ======================================================================
// Generic C[M,N] = A[M,K] @ B[K,N] + bias[N], tf32 tensor cores.
// Block tile 128x64, 8 warps (4x2), warp tile 32x32, K-tile 32.
// ======================================================================
#define BM 128
#define BN 64
#define BKt 32

__global__ __launch_bounds__(256) void gemm_tf32(
    const float* __restrict__ A, const float* __restrict__ Bw,
    const float* __restrict__ bias, float* __restrict__ C,
    int M, int N, int K)
{
    __shared__ float As[BM][BKt + 4];
    __shared__ float Bs[BKt][BN + 4];

    const int tid  = threadIdx.x;
    const int lane = tid & 31;
    const int warp = tid >> 5;
    const int wm = warp & 3;
    const int wn = warp >> 2;
    const int bm = blockIdx.y, bn = blockIdx.x;
    const int g  = lane >> 2;
    const int tg = lane & 3;

    const float* Ag = A + (size_t)bm * BM * K;
    const float* Bg = Bw + (size_t)bn * BN;

    float acc[2][4][4];
#pragma unroll
    for (int i = 0; i < 2; i++)
#pragma unroll
        for (int j = 0; j < 4; j++)
#pragma unroll
            for (int r = 0; r < 4; r++) acc[i][j][r] = 0.f;

    for (int kt = 0; kt < K; kt += BKt) {
#pragma unroll
        for (int i = 0; i < 4; i++) {
            int f4  = tid + i * 256;
            int row = f4 >> 3;
            int kc  = (f4 & 7) << 2;
            float4 v = *(const float4*)(Ag + (size_t)row * K + kt + kc);
            As[row][kc + 0] = __uint_as_float(f2tf(v.x));
            As[row][kc + 1] = __uint_as_float(f2tf(v.y));
            As[row][kc + 2] = __uint_as_float(f2tf(v.z));
            As[row][kc + 3] = __uint_as_float(f2tf(v.w));
        }
#pragma unroll
        for (int i = 0; i < 2; i++) {
            int f4  = tid + i * 256;
            int row = f4 >> 4;
            int nc  = (f4 & 15) << 2;
            float4 v = *(const float4*)(Bg + (size_t)(kt + row) * N + nc);
            Bs[row][nc + 0] = __uint_as_float(f2tf(v.x));
            Bs[row][nc + 1] = __uint_as_float(f2tf(v.y));
            Bs[row][nc + 2] = __uint_as_float(f2tf(v.z));
            Bs[row][nc + 3] = __uint_as_float(f2tf(v.w));
        }
        __syncthreads();

#pragma unroll
        for (int ks = 0; ks < 4; ks++) {
            const int k0 = ks * 8;
            unsigned a[2][4], b[4][2];
#pragma unroll
            for (int mi = 0; mi < 2; mi++) {
                int m0 = wm * 32 + mi * 16;
                a[mi][0] = __float_as_uint(As[m0 + g    ][k0 + tg    ]);
                a[mi][1] = __float_as_uint(As[m0 + g + 8][k0 + tg    ]);
                a[mi][2] = __float_as_uint(As[m0 + g    ][k0 + tg + 4]);
                a[mi][3] = __float_as_uint(As[m0 + g + 8][k0 + tg + 4]);
            }
#pragma unroll
            for (int ni = 0; ni < 4; ni++) {
                int n0 = wn * 32 + ni * 8;
                b[ni][0] = __float_as_uint(Bs[k0 + tg    ][n0 + g]);
                b[ni][1] = __float_as_uint(Bs[k0 + tg + 4][n0 + g]);
            }
#pragma unroll
            for (int mi = 0; mi < 2; mi++)
#pragma unroll
                for (int ni = 0; ni < 4; ni++)
                    asm volatile(
                        "mma.sync.aligned.m16n8k8.row.col.f32.tf32.tf32.f32 "
                        "{%0,%1,%2,%3},{%4,%5,%6,%7},{%8,%9},{%0,%1,%2,%3};"
                        : "+f"(acc[mi][ni][0]), "+f"(acc[mi][ni][1]),
                          "+f"(acc[mi][ni][2]), "+f"(acc[mi][ni][3])
                        : "r"(a[mi][0]), "r"(a[mi][1]), "r"(a[mi][2]), "r"(a[mi][3]),
                          "r"(b[ni][0]), "r"(b[ni][1]));
        }
        __syncthreads();
    }

#pragma unroll
    for (int mi = 0; mi < 2; mi++) {
        int r0 = bm * BM + wm * 32 + mi * 16 + g;
#pragma unroll
        for (int ni = 0; ni < 4; ni++) {
            int c0 = bn * BN + wn * 32 + ni * 8 + tg * 2;
            float b0 = bias[c0], b1 = bias[c0 + 1];
            *(float2*)(C + (size_t)r0 * N + c0) =
                make_float2(acc[mi][ni][0] + b0, acc[mi][ni][1] + b1);
            *(float2*)(C + (size_t)(r0 + 8) * N + c0) =
                make_float2(acc[mi][ni][2] + b0, acc[mi][ni][3] + b1);
        }
    }
}

// ======================================================================
// Wdec = lstm_k + lstm_rk (elementwise, float4)
// ======================================================================
__global__ void add_w(const float* __restrict__ a, const float* __restrict__ b,
                      float* __restrict__ o, int n4)
{
    int i = blockIdx.x * blockDim.x + threadIdx.x;
    if (i < n4) {
        float4 x = ((const float4*)a)[i];
        float4 y = ((const float4*)b)[i];
        ((float4*)o)[i] = make_float4(x.x + y.x, x.y + y.y, x.z + y.z, x.w + y.w);
    }
}

// ======================================================================
// Persistent recurrence kernel (rewritten):
//  - 128 blocks x 256 threads (8 warps = 2/SMSP)
//  - block j owns hidden columns [4j, 4j+4)  (16 z-columns across 4 gates)
//  - W enc/dec slices (32KB each) staged in SHARED once, reused 192 steps
//  - split-K: warps 0-3 do k<256, warps 4-7 do k>=256; reduce via shared
//  - inner loop uses packed fma.rn.f32x2 (2 MACs/instr, exact fp32)
//  - h[b][n] in global, double buffered; staged to shared each step (ldcg)
// ======================================================================
__device__ __forceinline__ void grid_barrier()
{
    __syncthreads();
    if (threadIdx.x == 0) {
        __threadfence();
        unsigned my = atomicAdd(&g_arrive, 1u) + 1u;
        unsigned need = (my + RGRID - 1u) / RGRID;
        if ((my % RGRID) == 0u) {
            atomicAdd(&g_release, 1u);
        } else {
            while (((volatile unsigned*)&g_release)[0] < need) { __nanosleep(40); }
        }
        __threadfence();
    }
    __syncthreads();
}

__device__ __forceinline__ float sigf(float x) { return 1.f / (1.f + expf(-x)); }

__global__ __launch_bounds__(256, 1) void recurrence(
    const float* __restrict__ Wenc,   // lstm_rk [512][2048]
    const float* __restrict__ Wdec,   // [512][2048]
    const float* __restrict__ xk,     // [B*H][2048] (bias folded in)
    const float* __restrict__ lb,     // lstm_b [2048]
    float* __restrict__ preds)        // [B][P][N]
{
    extern __shared__ float sm[];
    float* wEnc = sm;                  //  8192 floats (512 x 16)
    float* wDec = sm + 8192;           //  8192 floats
    float* hsh  = sm + 16384;          // 32 x 516 = 16512 floats
    float* zsf  = sm + 32896;          // 8 x 32 x 4 = 1024 floats

    const int tid = threadIdx.x;
    const int b   = tid & 31;
    const int g   = (tid >> 5) & 3;
    const int kg  = tid >> 7;          // split-K group (0/1)
    const int nc0 = blockIdx.x * 4;

    // ---- stage W slices into shared (once) ----
    for (int i = tid; i < 2048; i += 256) {
        int k = i >> 2, gg = i & 3;
        *(float4*)&wEnc[k * 16 + gg * 4] =
            *(const float4*)(Wenc + (size_t)k * G4N_ + gg * 512 + nc0);
        *(float4*)&wDec[k * 16 + gg * 4] =
            *(const float4*)(Wdec + (size_t)k * G4N_ + gg * 512 + nc0);
    }

    // ---- init ----
    const int cu = tid >> 5;           // update-role column (valid for tid<128)
    float lbr[4], cst = 0.f;
    if (tid < 128) {
        d_h[0][(size_t)b * N_ + nc0 + cu] = 0.f;
#pragma unroll
        for (int q = 0; q < 4; q++) lbr[q] = lb[q * 512 + nc0 + cu];
    }
    grid_barrier();

    for (int s = 0; s < H_ + P_; s++) {
        // ---- stage h[b][n] -> hsh[b][n] (stride 516), bypass L1 ----
        const float4* hg = (const float4*)d_h[s & 1];
#pragma unroll
        for (int i = 0; i < 16; i++) {
            int idx = tid + i * 256;       // idx = b*128 + n4
            int bb = idx >> 7, n4 = idx & 127;
            float4 v = __ldcg(hg + idx);
            *(float4*)&hsh[bb * HS_ + n4 * 4] = v;
        }
        // ---- prefetch per-step additive term (xk row or lstm_b) ----
        float pf[4];
        if (tid < 128) {
            if (s < H_) {
                const float* xp = xk + ((size_t)b * H_ + s) * G4N_ + nc0 + cu;
                pf[0] = __ldg(xp);
                pf[1] = __ldg(xp + 512);
                pf[2] = __ldg(xp + 1024);
                pf[3] = __ldg(xp + 1536);
            } else {
                pf[0] = lbr[0]; pf[1] = lbr[1]; pf[2] = lbr[2]; pf[3] = lbr[3];
            }
        }
        __syncthreads();

        // ---- z partial: 4 columns (g*512 + nc0 .. +4) over K/2, packed f32x2 ----
        const float* Wb = (s < H_) ? wEnc : wDec;
        const float* wp = Wb + g * 4 + (kg * 256) * 16;
        const float* hr = hsh + b * HS_ + kg * 256;
        ull a01 = 0ull, a23 = 0ull;
#pragma unroll 8
        for (int kk = 0; kk < 256; kk += 4) {
            float4 h4 = *(const float4*)(hr + kk);
#pragma unroll
            for (int j = 0; j < 4; j++) {
                ulonglong2 w = *(const ulonglong2*)(wp + (kk + j) * 16);
                float hv = (j == 0) ? h4.x : (j == 1) ? h4.y : (j == 2) ? h4.z : h4.w;
                ull hh;
                asm("mov.b64 %0, {%1,%1};" : "=l"(hh) : "f"(hv));
                asm("fma.rn.f32x2 %0, %1, %2, %0;" : "+l"(a01) : "l"(hh), "l"(w.x));
                asm("fma.rn.f32x2 %0, %1, %2, %0;" : "+l"(a23) : "l"(hh), "l"(w.y));
            }
        }
        // unpack and stash partials
        {
            float z0, z1, z2, z3;
            asm("mov.b64 {%0,%1}, %2;" : "=f"(z0), "=f"(z1) : "l"(a01));
            asm("mov.b64 {%0,%1}, %2;" : "=f"(z2), "=f"(z3) : "l"(a23));
            float4* zp = (float4*)&zsf[((kg * 4 + g) * 32 + b) * 4];
            *zp = make_float4(z0, z1, z2, z3);
        }
        __syncthreads();

        // ---- cell update: thread (b, cu) handles hidden col nc0+cu ----
        if (tid < 128) {
            float z[4];
#pragma unroll
            for (int q = 0; q < 4; q++)
                z[q] = zsf[((q * 32 + b) * 4) + cu]
                     + zsf[(((4 + q) * 32 + b) * 4) + cu]
                     + pf[q];
            float ii = sigf(z[0]), ff = sigf(z[1]);
            float gg = tanhf(z[2]), oo = sigf(z[3]);
            cst = ff * cst + ii * gg;
            float hn = oo * tanhf(cst);
            d_h[(s + 1) & 1][(size_t)b * N_ + nc0 + cu] = hn;
            if (s >= H_)
                preds[((size_t)b * P_ + (s - H_)) * N_ + nc0 + cu] = hn;
        }
        grid_barrier();
    }
}

// ======================================================================
// launch
// ======================================================================
extern "C" void kernel_launch(void* const* d_in, const int* in_sizes, int n_in,
                              void* d_out, int out_size)
{
    const float* x       = (const float*)d_in[0];
    const float* conv_w  = (const float*)d_in[1];
    const float* conv_b  = (const float*)d_in[2];
    const float* lstm_k  = (const float*)d_in[3];
    const float* lstm_rk = (const float*)d_in[4];
    const float* lstm_b  = (const float*)d_in[5];
    const float* dense_w = (const float*)d_in[6];
    const float* dense_b = (const float*)d_in[7];
    float* out = (float*)d_out;

    float *xr, *xk, *wdec, *preds;
    cudaGetSymbolAddress((void**)&xr,    d_xr);
    cudaGetSymbolAddress((void**)&xk,    d_xk);
    cudaGetSymbolAddress((void**)&wdec,  d_wdec);
    cudaGetSymbolAddress((void**)&preds, d_preds);

    const int RSMEM = (8192 + 8192 + 16512 + 1024) * 4;  // 135680 B
    cudaFuncSetAttribute(recurrence, cudaFuncAttributeMaxDynamicSharedMemorySize, RSMEM);

    // 1) xr = reshape(x) @ conv_w + conv_b     [5376,4096]x[4096,512]
    {
        dim3 grid(N_ / BN, MR_ / BM);
        gemm_tf32<<<grid, 256>>>(x, conv_w, conv_b, xr, MR_, N_, KIN_);
    }
    // 2) xk = xr @ lstm_k + lstm_b             [5376,512]x[512,2048]
    {
        dim3 grid(G4N_ / BN, MR_ / BM);
        gemm_tf32<<<grid, 256>>>(xr, lstm_k, lstm_b, xk, MR_, G4N_, N_);
    }
    // 3) Wdec = lstm_k + lstm_rk
    {
        int n4 = (N_ * G4N_) / 4;
        add_w<<<(n4 + 255) / 256, 256>>>(lstm_k, lstm_rk, wdec, n4);
    }
    // 4) encoder (168 steps) + decoder (24 steps), persistent
    recurrence<<<RGRID, 256, RSMEM>>>(lstm_rk, wdec, xk, lstm_b, preds);
    // 5) out = preds @ dense_w + dense_b       [768,512]x[512,512]
    {
        dim3 grid(N_ / BN, (B_ * P_) / BM);
        gemm_tf32<<<grid, 256>>>(preds, dense_w, dense_b, out, B_ * P_, N_, N_);
    }
}